// round 9
// baseline (speedup 1.0000x reference)
#include <cuda_runtime.h>
#include <cstdint>

// Problem constants (fixed by the dataset)
constexpr int D      = 128;     // embed size
constexpr int H      = 256;     // hidden size
constexpr int NODES  = 8192;    // 2*B
constexpr int BP     = 4096;    // pairs
constexpr int T_EDG  = NODES * 32;
constexpr int K1     = 3 * D;   // 384
constexpr int K2     = 2 * H;   // 512

// Scratch: packed weights + fused bias only (A1 intermediate eliminated)
__device__ float g_W1p[K1 * H];   // W1 packed in mma-fragment order
__device__ float g_Wrp[K2 * H];   // Wr packed in mma-fragment order
__device__ float g_b1[H];

__device__ __forceinline__ uint32_t f2tf32(float f) {
    uint32_t u;
    asm("cvt.rna.tf32.f32 %0, %1;" : "=r"(u) : "f"(f));
    return u;
}
__device__ __forceinline__ float cvt_tf32(float f) {
    return __uint_as_float(f2tf32(f));
}

// ---------------------------------------------------------------------------
// Kernel 0: pack weights into mma-fragment order + fuse bias.
// Packed layout (per BK=16 tile t):
//   dst = ((t*2 + ks)*32 + j)*64 + lane*2 + r
//   src = W[k][col], k = t*16 + ks*8 + (lane&3) + r*4, col = j*8 + (lane>>2)
// ---------------------------------------------------------------------------
__global__ void prep_w(const float* __restrict__ Wt, const float* __restrict__ Wn,
                       const float* __restrict__ Wr,
                       const float* __restrict__ bt, const float* __restrict__ bn) {
    const int gt = blockIdx.x * blockDim.x + threadIdx.x;
    const int w1_sz = K1 * H;         // 98304
    const int wr_sz = K2 * H;         // 131072
    if (gt < w1_sz) {
        const int r    = gt & 1;
        const int lane = (gt >> 1) & 31;
        const int j    = (gt >> 6) & 31;
        const int ks   = (gt >> 11) & 1;
        const int t    = gt >> 12;
        const int k    = t * 16 + ks * 8 + (lane & 3) + r * 4;
        const int col  = j * 8 + (lane >> 2);
        const float v  = (k < D) ? Wt[k * H + col] : Wn[(k - D) * H + col];
        g_W1p[gt] = cvt_tf32(v);
    } else if (gt < w1_sz + wr_sz) {
        const int idx  = gt - w1_sz;
        const int r    = idx & 1;
        const int lane = (idx >> 1) & 31;
        const int j    = (idx >> 6) & 31;
        const int ks   = (idx >> 11) & 1;
        const int t    = idx >> 12;
        const int k    = t * 16 + ks * 8 + (lane & 3) + r * 4;
        const int col  = j * 8 + (lane >> 2);
        g_Wrp[idx] = cvt_tf32(Wr[k * H + col]);
    }
    if (gt < H) g_b1[gt] = bt[gt] + bn[gt];
}

// ---------------------------------------------------------------------------
__device__ __forceinline__ void cp16(void* smem, const void* gmem) {
    uint32_t s = (uint32_t)__cvta_generic_to_shared(smem);
    asm volatile("cp.async.cg.shared.global [%0], [%1], 16;" :: "r"(s), "l"(gmem));
}
__device__ __forceinline__ void mma_tf32(float* a4, uint32_t a0, uint32_t a1,
                                         uint32_t a2, uint32_t a3,
                                         uint32_t b0, uint32_t b1) {
    asm volatile(
        "mma.sync.aligned.m16n8k8.row.col.f32.tf32.tf32.f32 "
        "{%0,%1,%2,%3}, {%4,%5,%6,%7}, {%8,%9}, {%0,%1,%2,%3};"
        : "+f"(a4[0]), "+f"(a4[1]), "+f"(a4[2]), "+f"(a4[3])
        : "r"(a0), "r"(a1), "r"(a2), "r"(a3), "r"(b0), "r"(b1));
}

// ---------------------------------------------------------------------------
// MEGA-FUSED kernel: one CTA = 32 nodes = 16 pairs. 256 threads, 256 CTAs.
//   Stage A (gather): 64 warp-tasks (32 nodes x {E,R}) -> A1 tile in SMEM
//   Stage B (phase 1): nodeTile[32,256] = tf32(relu(A1tile @ W1 + b1)) -> SMEM
//   Stage C (phase 2): out[16,256] = relu(pairview(nodeTile) @ Wr + br)
// A1 tile: stride 388 (mod 32 == 4 -> conflict-free frag loads).
// sN (stride 258) aliases the A1 tile region (A1 fully consumed first).
// ---------------------------------------------------------------------------
constexpr int BK     = 16;
constexpr int STAGES = 3;
constexpr int BM     = 32;              // nodes per CTA
constexpr int SA1    = 388;             // A1 tile stride
constexpr int SN     = 258;             // node tile stride (aliases A1)
constexpr int A1_FLOATS = BM * SA1;     // 12416
constexpr int B_SZ   = BK * H;          // 4096 per stage (packed, linear)
constexpr int FUSED_SMEM = (A1_FLOATS + STAGES * B_SZ) * 4;   // 98816 B

__global__ void __launch_bounds__(256, 2)
fused_all(const float* __restrict__ E, const float* __restrict__ R,
          const int* __restrict__ ents,
          const int* __restrict__ nent,
          const int* __restrict__ nrel,
          const int* __restrict__ offs,
          const float* __restrict__ W1p, const float* __restrict__ b1g,
          const float* __restrict__ Wrp, const float* __restrict__ br,
          float* __restrict__ out) {
    constexpr int THREADS = 256;

    extern __shared__ float smem[];
    float* sA1 = smem;                      // [32][SA1]; later aliased as sN [32][SN]
    float* sBb = smem + A1_FLOATS;          // STAGES * B_SZ

    const int tid  = threadIdx.x;
    const int wid  = tid >> 5;
    const int lane = tid & 31;
    const int grp  = lane >> 2;
    const int tg   = lane & 3;
    const int by   = blockIdx.x;

    auto issueB = [&](const float* Wsrc, int t, int stg) {
        float* sB = sBb + stg * B_SZ;
        const float* src = Wsrc + (size_t)t * B_SZ;
        #pragma unroll
        for (int l = 0; l < 4; l++) {       // 4096 floats / (256 thr * 4) = 4
            int o = (tid + l * THREADS) * 4;
            cp16(&sB[o], src + o);
        }
    };

    // Prime phase-1 weight pipeline BEFORE gather (lands during gather).
    #pragma unroll
    for (int s = 0; s < STAGES - 1; s++) {
        issueB(W1p, s, s);
        asm volatile("cp.async.commit_group;");
    }

    // ========================= STAGE A: gather ==============================
    // 64 tasks: task = nl*2 + (0:E / 1:R); warp w handles tasks w, w+8, ...
    {
        const float4* E4 = (const float4*)E;
        const float4* R4 = (const float4*)R;
        for (int task = wid; task < 2 * BM; task += 8) {
            const int nl   = task >> 1;
            const int node = by * BM + nl;
            const int start = offs[node];
            const int end   = (node + 1 < NODES) ? offs[node + 1] : T_EDG;
            const int cnt   = end - start;
            const float inv = 1.0f / (float)(cnt > 0 ? cnt : 1);
            float* row = sA1 + nl * SA1;

            if ((task & 1) == 0) {          // E-task: self + neighbor-entity mean
                float4 s = make_float4(0.f, 0.f, 0.f, 0.f);
                if (cnt == 32) {
                    const int idx = nent[start + lane];
                    #pragma unroll 8
                    for (int j = 0; j < 32; j++) {
                        const int ie = __shfl_sync(0xffffffffu, idx, j);
                        float4 v = __ldg(&E4[(size_t)ie * (D / 4) + lane]);
                        s.x += v.x; s.y += v.y; s.z += v.z; s.w += v.w;
                    }
                } else {
                    for (int base = start; base < end; base += 32) {
                        const int rem = end - base;
                        const int n   = rem < 32 ? rem : 32;
                        const int idx = (lane < rem) ? nent[base + lane] : 0;
                        for (int j = 0; j < n; j++) {
                            const int ie = __shfl_sync(0xffffffffu, idx, j);
                            float4 v = __ldg(&E4[(size_t)ie * (D / 4) + lane]);
                            s.x += v.x; s.y += v.y; s.z += v.z; s.w += v.w;
                        }
                    }
                }
                float4 e = __ldg(&E4[(size_t)ents[node] * (D / 4) + lane]);
                float4 o0, o1;
                o0.x = cvt_tf32(e.x);       o0.y = cvt_tf32(e.y);
                o0.z = cvt_tf32(e.z);       o0.w = cvt_tf32(e.w);
                o1.x = cvt_tf32(s.x * inv); o1.y = cvt_tf32(s.y * inv);
                o1.z = cvt_tf32(s.z * inv); o1.w = cvt_tf32(s.w * inv);
                *(float4*)(row + lane * 4)     = o0;
                *(float4*)(row + D + lane * 4) = o1;
            } else {                        // R-task: relation mean (L2-resident)
                float4 s = make_float4(0.f, 0.f, 0.f, 0.f);
                if (cnt == 32) {
                    const int idx = nrel[start + lane];
                    #pragma unroll 8
                    for (int j = 0; j < 32; j++) {
                        const int ir = __shfl_sync(0xffffffffu, idx, j);
                        float4 v = __ldg(&R4[(size_t)ir * (D / 4) + lane]);
                        s.x += v.x; s.y += v.y; s.z += v.z; s.w += v.w;
                    }
                } else {
                    for (int base = start; base < end; base += 32) {
                        const int rem = end - base;
                        const int n   = rem < 32 ? rem : 32;
                        const int idx = (lane < rem) ? nrel[base + lane] : 0;
                        for (int j = 0; j < n; j++) {
                            const int ir = __shfl_sync(0xffffffffu, idx, j);
                            float4 v = __ldg(&R4[(size_t)ir * (D / 4) + lane]);
                            s.x += v.x; s.y += v.y; s.z += v.z; s.w += v.w;
                        }
                    }
                }
                float4 o2;
                o2.x = cvt_tf32(s.x * inv); o2.y = cvt_tf32(s.y * inv);
                o2.z = cvt_tf32(s.z * inv); o2.w = cvt_tf32(s.w * inv);
                *(float4*)(row + 2 * D + lane * 4) = o2;
            }
        }
    }
    __syncthreads();   // A1 tile complete

    // ========================= STAGE B: phase 1 =============================
    // warps 2x4: wm = wid&1, wn = wid>>1; warp tile 16x64 (acc[8][4])
    {
        const int wm = wid & 1;
        const int wn = wid >> 1;

        float acc[8][4];
        #pragma unroll
        for (int j = 0; j < 8; j++)
            #pragma unroll
            for (int c = 0; c < 4; c++) acc[j][c] = 0.f;

        const int nt1 = K1 / BK;   // 24
        const int rb  = wm * 16 + grp;

        for (int t = 0; t < nt1; t++) {
            asm volatile("cp.async.wait_group %0;" :: "n"(STAGES - 2));
            __syncthreads();
            const int nt = t + STAGES - 1;
            if (nt < nt1) issueB(W1p, nt, nt % STAGES);
            asm volatile("cp.async.commit_group;");

            const float* sB = sBb + (t % STAGES) * B_SZ;
            const int kb = t * BK;
            #pragma unroll
            for (int ks = 0; ks < 2; ks++) {
                uint32_t a0 = __float_as_uint(sA1[(rb + 0) * SA1 + kb + ks * 8 + tg]);
                uint32_t a1 = __float_as_uint(sA1[(rb + 8) * SA1 + kb + ks * 8 + tg]);
                uint32_t a2 = __float_as_uint(sA1[(rb + 0) * SA1 + kb + ks * 8 + tg + 4]);
                uint32_t a3 = __float_as_uint(sA1[(rb + 8) * SA1 + kb + ks * 8 + tg + 4]);
                #pragma unroll
                for (int jl = 0; jl < 8; jl++) {
                    const int j = wn * 8 + jl;
                    float2 b = *(const float2*)(&sB[((ks * 32 + j) << 6) + lane * 2]);
                    mma_tf32(acc[jl], a0, a1, a2, a3,
                             __float_as_uint(b.x), __float_as_uint(b.y));
                }
            }
        }

        asm volatile("cp.async.wait_group 0;");
        __syncthreads();   // all A1 reads done before sN overwrites the region

        // epilogue 1: bias + relu + tf32 -> sN (aliases sA1 region)
        float* sN = sA1;
        #pragma unroll
        for (int jl = 0; jl < 8; jl++) {
            const int c = wn * 64 + jl * 8 + tg * 2;
            const float b0 = b1g[c], b1v = b1g[c + 1];
            float2 v0, v1;
            v0.x = cvt_tf32(fmaxf(acc[jl][0] + b0, 0.f));
            v0.y = cvt_tf32(fmaxf(acc[jl][1] + b1v, 0.f));
            v1.x = cvt_tf32(fmaxf(acc[jl][2] + b0, 0.f));
            v1.y = cvt_tf32(fmaxf(acc[jl][3] + b1v, 0.f));
            *(float2*)(&sN[(rb + 0) * SN + c]) = v0;
            *(float2*)(&sN[(rb + 8) * SN + c]) = v1;
        }
        __syncthreads();
    }

    // ========================= STAGE C: phase 2 =============================
    // 16 pairs x 256; warps 1x8 (wn2 = wid); warp tile 16x32 (acc[4][4])
    {
        const float* sN = sA1;
        const int wn2 = wid;

        float acc[4][4];
        #pragma unroll
        for (int j = 0; j < 4; j++)
            #pragma unroll
            for (int c = 0; c < 4; c++) acc[j][c] = 0.f;

        const int nt2 = K2 / BK;   // 32
        #pragma unroll
        for (int s = 0; s < STAGES - 1; s++) {
            issueB(Wrp, s, s);
            asm volatile("cp.async.commit_group;");
        }

        for (int t = 0; t < nt2; t++) {
            asm volatile("cp.async.wait_group %0;" :: "n"(STAGES - 2));
            __syncthreads();
            const int nt = t + STAGES - 1;
            if (nt < nt2) issueB(Wrp, nt, nt % STAGES);
            asm volatile("cp.async.commit_group;");

            const float* sB = sBb + (t % STAGES) * B_SZ;
            #pragma unroll
            for (int ks = 0; ks < 2; ks++) {
                const int k  = t * BK + ks * 8;
                const int h  = (k >= 256) ? 1 : 0;
                const int kk = k & 255;
                uint32_t a0 = __float_as_uint(sN[(2 * (grp + 0) + h) * SN + kk + tg]);
                uint32_t a1 = __float_as_uint(sN[(2 * (grp + 8) + h) * SN + kk + tg]);
                uint32_t a2 = __float_as_uint(sN[(2 * (grp + 0) + h) * SN + kk + tg + 4]);
                uint32_t a3 = __float_as_uint(sN[(2 * (grp + 8) + h) * SN + kk + tg + 4]);
                #pragma unroll
                for (int jl = 0; jl < 4; jl++) {
                    const int j = wn2 * 4 + jl;
                    float2 b = *(const float2*)(&sB[((ks * 32 + j) << 6) + lane * 2]);
                    mma_tf32(acc[jl], a0, a1, a2, a3,
                             __float_as_uint(b.x), __float_as_uint(b.y));
                }
            }
        }

        // epilogue 2: bias + relu -> gmem
        const int prow = by * 16 + grp;
        #pragma unroll
        for (int jl = 0; jl < 4; jl++) {
            const int c = wn2 * 32 + jl * 8 + tg * 2;
            const float b0 = br[c], b1v = br[c + 1];
            float2 v0, v1;
            v0.x = fmaxf(acc[jl][0] + b0, 0.f);
            v0.y = fmaxf(acc[jl][1] + b1v, 0.f);
            v1.x = fmaxf(acc[jl][2] + b0, 0.f);
            v1.y = fmaxf(acc[jl][3] + b1v, 0.f);
            *(float2*)(out + (size_t)(prow + 0) * H + c) = v0;
            *(float2*)(out + (size_t)(prow + 8) * H + c) = v1;
        }
    }
}

// ---------------------------------------------------------------------------
extern "C" void kernel_launch(void* const* d_in, const int* in_sizes, int n_in,
                              void* d_out, int out_size) {
    const float* E    = (const float*)d_in[0];
    const float* R    = (const float*)d_in[1];
    const float* Wt   = (const float*)d_in[2];
    const float* bt   = (const float*)d_in[3];
    const float* Wn   = (const float*)d_in[4];
    const float* bn   = (const float*)d_in[5];
    const float* Wr   = (const float*)d_in[6];
    const float* br   = (const float*)d_in[7];
    const int*   ents = (const int*)d_in[8];
    const int*   nent = (const int*)d_in[9];
    const int*   nrel = (const int*)d_in[10];
    const int*   offs = (const int*)d_in[11];
    float* out = (float*)d_out;

    float *W1p, *Wrp, *b1;
    cudaGetSymbolAddress((void**)&W1p, g_W1p);
    cudaGetSymbolAddress((void**)&Wrp, g_Wrp);
    cudaGetSymbolAddress((void**)&b1,  g_b1);

    cudaFuncSetAttribute(fused_all,
                         cudaFuncAttributeMaxDynamicSharedMemorySize, FUSED_SMEM);

    // 0) pack weights + fuse bias (small, ~0.9 MB)
    prep_w<<<((K1 + K2) * H + 255) / 256, 256>>>(Wt, Wn, Wr, bt, bn);

    // 1) mega-fused gather + 2-layer MLP: 256 CTAs x 256 threads, 2 CTAs/SM
    fused_all<<<NODES / BM, 256, FUSED_SMEM>>>(E, R, ents, nent, nrel, offs,
                                               W1p, b1, Wrp, br, out);
}